// round 17
// baseline (speedup 1.0000x reference)
#include <cuda_runtime.h>
#include <cstdint>

// Problem constants
#define BS   64
#define IC   256     // in_dim
#define NPIX 256     // pixels (I)
#define J    64      // out caps
#define D2   32      // dim per cap
#define NCHK 4       // i-chunks
#define CW   64      // chunk width

// Global scratch
__device__ float g_L[(size_t)BS * J * NPIX];            // logits after iter-1
__device__ float g_xT[(size_t)BS * NPIX * IC];          // x transposed [b][i][ic]
__device__ float g_ypart[(size_t)BS * NCHK * J * IC];   // [b][ch][j][ic]
__device__ float g_cpart[(size_t)BS * NCHK * J];        // [b][ch][j]
__device__ float g_wtT[(size_t)BS * IC * J];            // [b][ic][j]
__device__ float g_beta[(size_t)BS * J];                // [b][j]

// ---------------------------------------------------------------------------
// f32x2 helpers
// ---------------------------------------------------------------------------
#define FFMA2(acc, aa, bb) \
    asm("fma.rn.f32x2 %0, %1, %2, %0;" : "+l"(acc) : "l"(aa), "l"(bb))
__device__ __forceinline__ unsigned long long dup2f(float s) {
    unsigned long long d;
    asm("mov.b64 %0, {%1, %1};" : "=l"(d) : "f"(s));
    return d;
}
__device__ __forceinline__ float2 unpk(unsigned long long v) {
    float2 r;
    asm("mov.b64 {%0, %1}, %2;" : "=f"(r.x), "=f"(r.y) : "l"(v));
    return r;
}

// ---------------------------------------------------------------------------
// Prep: transpose x[b][ic][i] -> g_xT[b][i][ic]  (runs once)
// ---------------------------------------------------------------------------
__global__ __launch_bounds__(256) void xt_prep(const float* __restrict__ x) {
    __shared__ float t[32][33];
    int b = blockIdx.z, i0 = blockIdx.x * 32, ic0 = blockIdx.y * 32;
    int tx = threadIdx.x, ty = threadIdx.y;   // 32 x 8
    #pragma unroll
    for (int q = 0; q < 4; q++)
        t[ty + q * 8][tx] = x[((size_t)b * IC + ic0 + ty + q * 8) * NPIX + i0 + tx];
    __syncthreads();
    #pragma unroll
    for (int q = 0; q < 4; q++) {
        int row = ty + q * 8;
        g_xT[((size_t)b * NPIX + i0 + row) * IC + ic0 + tx] = t[tx][row];
    }
}

// ---------------------------------------------------------------------------
// yd2: fused db + softmax + y per (64-px chunk, b). 512 thr, 2 CTAs/SM.
// smem UNION: phase1 wrT[ic][j] (64KB) -> phase3 xT[i][ic] (64KB).
// it==0: Lc = b_init                      ; softmax; y
// it==1: Lc = b_init + wtT.x + beta -> g_L; softmax; y
// it==2: Lc = g_L    + wtT.x + beta       ; softmax; y
// ---------------------------------------------------------------------------
#define CSP    68
#define U_O    0                      // union: wrT or xT   16384
#define CS_O   16384                  // cs [i=64][68]      4352
#define LC_O   (CS_O + CW * CSP)      // Lc [j=64][65]      4160
#define Y_SM_FLOATS (LC_O + J * 65)   // 24896 floats = 99,584 B

__global__ __launch_bounds__(512, 2) void yd2_kernel(
    const float* __restrict__ x, const float* __restrict__ Lsrc, int it)
{
    extern __shared__ float sm[];
    float* uf = sm + U_O;             // union buffer
    float* cs = sm + CS_O;
    float* Lc = sm + LC_O;

    const int ch   = blockIdx.x;
    const int b    = blockIdx.y;
    const int i0g  = ch * CW;
    const int tid  = threadIdx.x;
    const int w    = tid >> 5;
    const int lane = tid & 31;

    if (it) {
        // ---- phase 1a: load wrT (float4, coalesced) ----
        const float4* wsrc = reinterpret_cast<const float4*>(
            g_wtT + (size_t)b * IC * J);
        float4* u4 = reinterpret_cast<float4*>(uf);
        for (int e = tid; e < IC * J / 4; e += 512)
            u4[e] = wsrc[e];
        __syncthreads();

        // ---- phase 1b: db GEMM. warp: jb=(w&7)*8, px il=(w>>3)*32+lane ----
        const int jb = (w & 7) * 8;
        const int il = (w >> 3) * 32 + lane;
        const float* xp = x + (size_t)b * IC * NPIX + i0g + il;
        unsigned long long acc[4] = {0ull, 0ull, 0ull, 0ull};
        #pragma unroll 8
        for (int ic = 0; ic < IC; ic++) {
            unsigned long long xd = dup2f(xp[(size_t)ic * NPIX]);   // coalesced
            const ulonglong2* wp =
                reinterpret_cast<const ulonglong2*>(uf + ic * J + jb);  // bcast
            ulonglong2 w01 = wp[0], w23 = wp[1];
            FFMA2(acc[0], w01.x, xd);
            FFMA2(acc[1], w01.y, xd);
            FFMA2(acc[2], w23.x, xd);
            FFMA2(acc[3], w23.y, xd);
        }
        #pragma unroll
        for (int p = 0; p < 4; p++) {
            int j = jb + 2 * p;
            float2 dv = unpk(acc[p]);
            float l0 = Lsrc[((size_t)b * J + j) * NPIX + i0g + il]
                     + dv.x + g_beta[b * J + j];
            float l1 = Lsrc[((size_t)b * J + j + 1) * NPIX + i0g + il]
                     + dv.y + g_beta[b * J + j + 1];
            Lc[j * 65 + il]       = l0;
            Lc[(j + 1) * 65 + il] = l1;
            if (it == 1) {
                g_L[((size_t)b * J + j) * NPIX + i0g + il]     = l0;
                g_L[((size_t)b * J + j + 1) * NPIX + i0g + il] = l1;
            }
        }
        __syncthreads();
    } else {
        for (int e = tid; e < J * CW; e += 512) {
            int j = e >> 6, il = e & 63;
            Lc[j * 65 + il] = Lsrc[((size_t)b * J + j) * NPIX + i0g + il];
        }
        __syncthreads();
    }

    // ---- phase 2: softmax over j per pixel (8 thr/px, shfl reduce) ----
    {
        int i = tid >> 3, sub = tid & 7, jb2 = sub * 8;
        float m = -1e30f;
        #pragma unroll
        for (int jj = 0; jj < 8; jj++)
            m = fmaxf(m, Lc[(jb2 + jj) * 65 + i]);
        #pragma unroll
        for (int o = 1; o < 8; o <<= 1)
            m = fmaxf(m, __shfl_xor_sync(0xFFFFFFFFu, m, o));
        float ssum = 0.f;
        #pragma unroll
        for (int jj = 0; jj < 8; jj++) {
            float e = __expf(Lc[(jb2 + jj) * 65 + i] - m);
            cs[i * CSP + jb2 + jj] = e;
            ssum += e;
        }
        #pragma unroll
        for (int o = 1; o < 8; o <<= 1)
            ssum += __shfl_xor_sync(0xFFFFFFFFu, ssum, o);
        float rd = 1.0f / ssum;
        #pragma unroll
        for (int jj = 0; jj < 8; jj++)
            cs[i * CSP + jb2 + jj] *= rd;
    }
    __syncthreads();

    // ---- phase 3a: xT load into union (overwrites wrT) + Csum partial ----
    {
        const float4* xTb = reinterpret_cast<const float4*>(
            g_xT + ((size_t)b * NPIX + i0g) * IC);
        float4* u4 = reinterpret_cast<float4*>(uf);
        for (int e = tid; e < CW * IC / 4; e += 512)
            u4[e] = xTb[e];
    }
    if (tid < J) {
        float cc = 0.f;
        #pragma unroll 8
        for (int i2 = 0; i2 < CW; i2++) cc += cs[i2 * CSP + tid];
        g_cpart[((size_t)b * NCHK + ch) * J + tid] = cc;
    }
    __syncthreads();

    // ---- phase 3b: y GEMM. warp = 16-ic block; lane = j (2 j) ----
    {
        const int ic0 = w * 16;
        unsigned long long acc[2][8];
        #pragma unroll
        for (int h = 0; h < 2; h++)
            #pragma unroll
            for (int p = 0; p < 8; p++) acc[h][p] = 0ull;

        #pragma unroll 2
        for (int k = 0; k < CW; k++) {
            unsigned long long cd0 = dup2f(cs[k * CSP + lane]);
            unsigned long long cd1 = dup2f(cs[k * CSP + lane + 32]);
            const ulonglong2* xq =
                reinterpret_cast<const ulonglong2*>(uf + k * 256 + ic0);
            ulonglong2 x01 = xq[0], x23 = xq[1], x45 = xq[2], x67 = xq[3];
            FFMA2(acc[0][0], cd0, x01.x); FFMA2(acc[0][1], cd0, x01.y);
            FFMA2(acc[0][2], cd0, x23.x); FFMA2(acc[0][3], cd0, x23.y);
            FFMA2(acc[0][4], cd0, x45.x); FFMA2(acc[0][5], cd0, x45.y);
            FFMA2(acc[0][6], cd0, x67.x); FFMA2(acc[0][7], cd0, x67.y);
            FFMA2(acc[1][0], cd1, x01.x); FFMA2(acc[1][1], cd1, x01.y);
            FFMA2(acc[1][2], cd1, x23.x); FFMA2(acc[1][3], cd1, x23.y);
            FFMA2(acc[1][4], cd1, x45.x); FFMA2(acc[1][5], cd1, x45.y);
            FFMA2(acc[1][6], cd1, x67.x); FFMA2(acc[1][7], cd1, x67.y);
        }
        #pragma unroll
        for (int h = 0; h < 2; h++) {
            int j = lane + 32 * h;
            float* yr = g_ypart + (((size_t)b * NCHK + ch) * J + j) * IC + ic0;
            #pragma unroll
            for (int q = 0; q < 4; q++) {
                float2 e0 = unpk(acc[h][2 * q]);
                float2 e1 = unpk(acc[h][2 * q + 1]);
                *reinterpret_cast<float4*>(yr + 4 * q) =
                    make_float4(e0.x, e0.y, e1.x, e1.y);
            }
        }
    }
}

// ---------------------------------------------------------------------------
// S kernel: one CTA per (j, 16-batch group), 256 threads. Writes g_wtT.
// ---------------------------------------------------------------------------
#define WJ_O2   0
#define YS_O2   8320
#define VS_O2   12480
#define SS_O2   13008
#define CS_O2   13536
#define WB_O2   13552
#define S_SM_FLOATS 13584        // 54,336 B

__global__ __launch_bounds__(256) void s_kernel(
    const float* __restrict__ W, const float* __restrict__ Wb,
    float* __restrict__ out, int final_it)
{
    extern __shared__ float ss[];
    float* Wj  = ss + WJ_O2;
    float* ysm = ss + YS_O2;
    float* vsm = ss + VS_O2;
    float* ssm = ss + SS_O2;
    float* Cs  = ss + CS_O2;
    float* Wbj = ss + WB_O2;

    const int j   = blockIdx.x;
    const int b0  = blockIdx.y * 16;
    const int tid = threadIdx.x;

    for (int e = tid; e < D2 * IC; e += 256) {
        int d = e >> 8, ic = e & 255;
        Wj[d * 260 + ic] = W[(size_t)j * D2 * IC + e];
    }
    if (tid < D2) Wbj[tid] = Wb[j * D2 + tid];
    for (int e = tid; e < 16 * IC; e += 256) {
        int b = e >> 8, ic = e & 255;
        const float* yp = g_ypart + (((size_t)(b0 + b) * NCHK) * J + j) * IC + ic;
        ysm[b * 260 + ic] = (yp[0] + yp[(size_t)J * IC])
                          + (yp[2 * (size_t)J * IC] + yp[3 * (size_t)J * IC]);
    }
    if (tid < 16) {
        const float* cp = g_cpart + ((size_t)(b0 + tid) * NCHK) * J + j;
        Cs[tid] = (cp[0] + cp[J]) + (cp[2 * J] + cp[3 * J]);
    }
    __syncthreads();

    // stage2: s[b][d] = Wj[d,:].y[b,:] + Wb[d]*C[b]
    {
        int b = tid & 15, d0 = (tid >> 4) * 2;
        const float* y  = ysm + b * 260;
        const float* w0 = Wj + d0 * 260;
        const float* w1 = w0 + 260;
        float a0 = 0.f, a1 = 0.f;
        #pragma unroll 8
        for (int ic = 0; ic < IC; ic += 4) {
            float4 y4 = *reinterpret_cast<const float4*>(y + ic);
            float4 wa = *reinterpret_cast<const float4*>(w0 + ic);
            float4 wb = *reinterpret_cast<const float4*>(w1 + ic);
            a0 += y4.x * wa.x + y4.y * wa.y + y4.z * wa.z + y4.w * wa.w;
            a1 += y4.x * wb.x + y4.y * wb.y + y4.z * wb.z + y4.w * wb.w;
        }
        float C = Cs[b];
        ssm[b * 33 + d0]     = a0 + Wbj[d0] * C;
        ssm[b * 33 + d0 + 1] = a1 + Wbj[d0 + 1] * C;
    }
    __syncthreads();

    // squash: warp w handles b = 2w, 2w+1; lane = d
    {
        int w = tid >> 5, lane = tid & 31;
        #pragma unroll
        for (int h = 0; h < 2; h++) {
            int b = w * 2 + h;
            float sv = ssm[b * 33 + lane];
            float sq = sv * sv;
            #pragma unroll
            for (int o = 16; o; o >>= 1) sq += __shfl_xor_sync(0xFFFFFFFFu, sq, o);
            float scale = (sq / (1.0f + sq)) * rsqrtf(sq + 1e-8f);
            float vv = scale * sv;
            vsm[b * 33 + lane] = vv;
            if (final_it) out[((size_t)(b0 + b) * J + j) * D2 + lane] = vv;
            float bt = vv * Wbj[lane];
            #pragma unroll
            for (int o = 16; o; o >>= 1) bt += __shfl_xor_sync(0xFFFFFFFFu, bt, o);
            if (lane == 0) g_beta[(b0 + b) * J + j] = bt;
        }
    }
    __syncthreads();

    // stage4: wtT[b][ic][j] = sum_d v[b][d] * Wj[d][ic]
    if (!final_it) {
        int ic = tid;
        float wv[16];
        #pragma unroll
        for (int b = 0; b < 16; b++) wv[b] = 0.f;
        #pragma unroll 4
        for (int d = 0; d < D2; d++) {
            float wjv = Wj[d * 260 + ic];
            #pragma unroll
            for (int b = 0; b < 16; b++)
                wv[b] = fmaf(vsm[b * 33 + d], wjv, wv[b]);
        }
        #pragma unroll
        for (int b = 0; b < 16; b++)
            g_wtT[((size_t)(b0 + b) * IC + ic) * J + j] = wv[b];
    }
}

// ---------------------------------------------------------------------------
// Launch (7 kernels, graph-capturable, allocation-free)
// Inputs: x[64,256,16,16] f32, b_init[64,64,256] f32, W[2048,256] f32, Wb[2048] f32
// Output: v[64,64,32] f32
// ---------------------------------------------------------------------------
extern "C" void kernel_launch(void* const* d_in, const int* in_sizes, int n_in,
                              void* d_out, int out_size)
{
    const float* x      = (const float*)d_in[0];
    const float* b_init = (const float*)d_in[1];
    const float* W      = (const float*)d_in[2];
    const float* Wb     = (const float*)d_in[3];
    float* out = (float*)d_out;

    const int ysmem = Y_SM_FLOATS * (int)sizeof(float);   // 99,584 B
    const int ssmem = S_SM_FLOATS * (int)sizeof(float);   // 54,336 B
    cudaFuncSetAttribute(yd2_kernel, cudaFuncAttributeMaxDynamicSharedMemorySize, ysmem);
    cudaFuncSetAttribute(s_kernel,   cudaFuncAttributeMaxDynamicSharedMemorySize, ssmem);

    float* Lwork = nullptr;
    cudaGetSymbolAddress((void**)&Lwork, g_L);

    xt_prep<<<dim3(NPIX / 32, IC / 32, BS), dim3(32, 8)>>>(x);

    dim3 ygrid(NCHK, BS);         // 4 x 64 = 256 CTAs, 2/SM
    dim3 sgrid(J, 4);             // 64 x 4 = 256 CTAs

    yd2_kernel<<<ygrid, 512, ysmem>>>(x, b_init, 0);
    s_kernel<<<sgrid, 256, ssmem>>>(W, Wb, out, 0);
    yd2_kernel<<<ygrid, 512, ysmem>>>(x, b_init, 1);
    s_kernel<<<sgrid, 256, ssmem>>>(W, Wb, out, 0);
    yd2_kernel<<<ygrid, 512, ysmem>>>(x, Lwork, 2);
    s_kernel<<<sgrid, 256, ssmem>>>(W, Wb, out, 1);
}